// round 8
// baseline (speedup 1.0000x reference)
#include <cuda_runtime.h>
#include <cuda_bf16.h>
#include <cuda_fp16.h>
#include <stdint.h>
#include <math.h>

#define HEAD 128
#define CEMB 64
#define BATCH 8
#define TLEN 4096
#define BT (BATCH * TLEN)

#define BM 64               // q rows per CTA (4 warps x 16)
#define BN 32               // key tile
#define PITCHB 272
#define NITEMS 512          // 64 q-tiles x 8 batches

// ---------------- global scratch (static) ------------------------------------
__device__ __nv_bfloat16 g_qh[(size_t)BT * HEAD];
__device__ __nv_bfloat16 g_ql[(size_t)BT * HEAD];
__device__ __nv_bfloat16 g_kh[(size_t)BT * HEAD];
__device__ __nv_bfloat16 g_kl[(size_t)BT * HEAD];
__device__ __half        g_vh[(size_t)BT * HEAD];
__device__ __half        g_vl[(size_t)BT * HEAD];
__device__ unsigned int  g_ctr;

extern __shared__ char smem_raw[];

// ---------------- helpers ----------------------------------------------------
__device__ __forceinline__ uint32_t su32(const void* p) {
    uint32_t a;
    asm("{ .reg .u64 t; cvta.to.shared.u64 t, %1; cvt.u32.u64 %0, t; }"
        : "=r"(a) : "l"(p));
    return a;
}

__device__ __forceinline__ void mma_bf16(float* c, const uint32_t* a, const uint32_t* b) {
    asm volatile(
        "mma.sync.aligned.m16n8k16.row.col.f32.bf16.bf16.f32 "
        "{%0,%1,%2,%3}, {%4,%5,%6,%7}, {%8,%9}, {%0,%1,%2,%3};"
        : "+f"(c[0]), "+f"(c[1]), "+f"(c[2]), "+f"(c[3])
        : "r"(a[0]), "r"(a[1]), "r"(a[2]), "r"(a[3]), "r"(b[0]), "r"(b[1]));
}
__device__ __forceinline__ void mma_f16(float* c, const uint32_t* a, const uint32_t* b) {
    asm volatile(
        "mma.sync.aligned.m16n8k16.row.col.f32.f16.f16.f32 "
        "{%0,%1,%2,%3}, {%4,%5,%6,%7}, {%8,%9}, {%0,%1,%2,%3};"
        : "+f"(c[0]), "+f"(c[1]), "+f"(c[2]), "+f"(c[3])
        : "r"(a[0]), "r"(a[1]), "r"(a[2]), "r"(a[3]), "r"(b[0]), "r"(b[1]));
}

__device__ __forceinline__ void ldsm4(uint32_t* r, uint32_t addr) {
    asm volatile("ldmatrix.sync.aligned.m8n8.x4.shared.b16 {%0,%1,%2,%3}, [%4];"
                 : "=r"(r[0]), "=r"(r[1]), "=r"(r[2]), "=r"(r[3]) : "r"(addr));
}
__device__ __forceinline__ void ldsm4t(uint32_t* r, uint32_t addr) {
    asm volatile("ldmatrix.sync.aligned.m8n8.x4.trans.shared.b16 {%0,%1,%2,%3}, [%4];"
                 : "=r"(r[0]), "=r"(r[1]), "=r"(r[2]), "=r"(r[3]) : "r"(addr));
}

__device__ __forceinline__ uint32_t pack2(__nv_bfloat16 a, __nv_bfloat16 b) {
    __nv_bfloat162 t = __halves2bfloat162(a, b);
    return *reinterpret_cast<uint32_t*>(&t);
}
__device__ __forceinline__ uint32_t pack2h(__half a, __half b) {
    __half2 t = __halves2half2(a, b);
    return *reinterpret_cast<uint32_t*>(&t);
}

__device__ __forceinline__ float fexp2(float x) {
    float y;
    asm("ex2.approx.ftz.f32 %0, %1;" : "=f"(y) : "f"(x));
    return y;
}

#define CP_ASYNC16(dst, src) \
    asm volatile("cp.async.cg.shared.global [%0], [%1], 16;" :: "r"(dst), "l"(src))
#define CP_COMMIT() asm volatile("cp.async.commit_group;" ::: "memory")
#define CP_WAIT(n)  asm volatile("cp.async.wait_group %0;" :: "n"(n) : "memory")

__device__ __forceinline__ void split2(float v0, float v1, uint32_t& hi, uint32_t& lo) {
    __nv_bfloat16 h0 = __float2bfloat16(v0);
    __nv_bfloat16 h1 = __float2bfloat16(v1);
    hi = pack2(h0, h1);
    lo = pack2(__float2bfloat16(v0 - __bfloat162float(h0)),
               __float2bfloat16(v1 - __bfloat162float(h1)));
}
__device__ __forceinline__ void split2h(float v0, float v1, uint32_t& hi, uint32_t& lo) {
    __half h0 = __float2half_rn(v0);
    __half h1 = __float2half_rn(v1);
    hi = pack2h(h0, h1);
    lo = pack2h(__float2half_rn(v0 - __half2float(h0)),
                __float2half_rn(v1 - __half2float(h1)));
}

// ---------------------------------------------------------------------------
// Kernel 1: QKV projection on tensor cores (3-term split-bf16 math).
// Q/K written as bf16 hi/lo (log2e folded into Wq); V as fp16 hi/lo.
// Also resets the attn work counter (attn launches strictly after).
// ---------------------------------------------------------------------------
#define XPITCH 144
#define WPITCH 784
#define P_XH 0
#define P_XL (128 * XPITCH)
#define P_WH (2 * 128 * XPITCH)
#define P_WL (P_WH + 64 * WPITCH)
#define PROJ_SMEM (P_WL + 64 * WPITCH)

__global__ __launch_bounds__(256) void proj_kernel(
    const float* __restrict__ x,
    const float* __restrict__ Wq,
    const float* __restrict__ Wk,
    const float* __restrict__ Wv)
{
    char* sm = smem_raw;
    const uint32_t sb = su32(sm);
    const int tid  = threadIdx.x;
    const int wid  = tid >> 5;
    const int lane = tid & 31;
    const int gid  = lane >> 2;
    const int tig  = lane & 3;
    const int row0 = blockIdx.x * 128;
    const float qsc = rsqrtf((float)HEAD) * 1.4426950408889634f;

    if (blockIdx.x == 0 && tid == 0) g_ctr = 0u;

    #pragma unroll
    for (int ii = 0; ii < 8; ii++) {
        int i = tid + ii * 256;
        int r = i >> 4, c4 = i & 15;
        float4 v = ((const float4*)(x + (size_t)(row0 + r) * CEMB))[c4];
        uint32_t h0, l0, h1, l1;
        split2(v.x, v.y, h0, l0);
        split2(v.z, v.w, h1, l1);
        char* d = sm + P_XH + r * XPITCH + c4 * 8;
        *(uint32_t*)d = h0; *(uint32_t*)(d + 4) = h1;
        char* d2 = sm + P_XL + r * XPITCH + c4 * 8;
        *(uint32_t*)d2 = l0; *(uint32_t*)(d2 + 4) = l1;
    }
    #pragma unroll
    for (int ii = 0; ii < 24; ii++) {
        int i = tid + ii * 256;
        int r = i / 96, c4 = i % 96;
        int col = 4 * c4, a = col >> 7, lcol = col & 127;
        const float* ws = (a == 0 ? Wq : (a == 1 ? Wk : Wv)) + r * 128 + lcol;
        float4 v = *(const float4*)ws;
        if (a == 0) { v.x *= qsc; v.y *= qsc; v.z *= qsc; v.w *= qsc; }
        uint32_t h0, l0, h1, l1;
        split2(v.x, v.y, h0, l0);
        split2(v.z, v.w, h1, l1);
        char* d = sm + P_WH + r * WPITCH + col * 2;
        *(uint32_t*)d = h0; *(uint32_t*)(d + 4) = h1;
        char* d2 = sm + P_WL + r * WPITCH + col * 2;
        *(uint32_t*)d2 = l0; *(uint32_t*)(d2 + 4) = l1;
    }
    __syncthreads();

    const int wr0 = wid * 16;
    uint32_t axh[4][4], axl[4][4];
    {
        const int arow = (lane & 7) + ((lane >> 3) & 1) * 8;
        const int acol = (lane >> 4) * 8;
        #pragma unroll
        for (int ks = 0; ks < 4; ks++) {
            uint32_t ad = sb + P_XH + (wr0 + arow) * XPITCH + (ks * 16 + acol) * 2;
            ldsm4(axh[ks], ad);
            ldsm4(axl[ks], ad + (P_XL - P_XH));
        }
    }

    #pragma unroll
    for (int chunk = 0; chunk < 6; chunk++) {
        float c[8][4];
        #pragma unroll
        for (int i = 0; i < 8; i++)
            #pragma unroll
            for (int j = 0; j < 4; j++) c[i][j] = 0.f;

        #pragma unroll
        for (int ks = 0; ks < 4; ks++) {
            #pragma unroll
            for (int q = 0; q < 4; q++) {
                uint32_t wh[4], wl[4];
                const int i7 = lane & 7, sel = lane >> 3;
                uint32_t off = (uint32_t)((ks * 16 + i7 + ((sel & 1) << 3)) * WPITCH +
                                          (chunk * 64 + q * 16 + ((sel >> 1) << 3)) * 2);
                ldsm4t(wh, sb + P_WH + off);
                ldsm4t(wl, sb + P_WL + off);
                #pragma unroll
                for (int term = 0; term < 3; term++) {
                    const uint32_t* a = (term == 2) ? axl[ks] : axh[ks];
                    const uint32_t* bb = (term == 1) ? wl : wh;
                    mma_bf16(c[2 * q],     a, &bb[0]);
                    mma_bf16(c[2 * q + 1], a, &bb[2]);
                }
            }
        }

        const size_t rb = (size_t)(row0 + wr0 + gid) * HEAD;
        if (chunk < 4) {
            __nv_bfloat16* dh = (chunk < 2) ? g_qh : g_kh;
            __nv_bfloat16* dl = (chunk < 2) ? g_ql : g_kl;
            const int colbase = (chunk & 1) * 64;
            #pragma unroll
            for (int nb = 0; nb < 8; nb++) {
                const int col = colbase + 8 * nb + 2 * tig;
                uint32_t h, l;
                split2(c[nb][0], c[nb][1], h, l);
                *(uint32_t*)(dh + rb + col) = h;
                *(uint32_t*)(dl + rb + col) = l;
                split2(c[nb][2], c[nb][3], h, l);
                *(uint32_t*)(dh + rb + 8 * HEAD + col) = h;
                *(uint32_t*)(dl + rb + 8 * HEAD + col) = l;
            }
        } else {
            const int colbase = (chunk - 4) * 64;
            #pragma unroll
            for (int nb = 0; nb < 8; nb++) {
                const int col = colbase + 8 * nb + 2 * tig;
                uint32_t h, l;
                split2h(c[nb][0], c[nb][1], h, l);
                *(uint32_t*)(g_vh + rb + col) = h;
                *(uint32_t*)(g_vl + rb + col) = l;
                split2h(c[nb][2], c[nb][3], h, l);
                *(uint32_t*)(g_vh + rb + 8 * HEAD + col) = h;
                *(uint32_t*)(g_vl + rb + 8 * HEAD + col) = l;
            }
        }
    }
}

// ---------------------------------------------------------------------------
// Kernel 2: persistent flash attention; 128-thread CTAs, 2 per SM.
// QK bf16 3-term, PV fp16 2-term; QK(t+1) interleaved with PV(t); 3-slot ring.
// ---------------------------------------------------------------------------
#define BUFB (4 * BN * PITCHB)         // 34816 B
#define NBUF 3
#define ATTN_SMEM (NBUF * BUFB)        // 104448 B per CTA

__global__ __launch_bounds__(128, 1) void attn_kernel(float* __restrict__ out)
{
    char* sm = smem_raw;
    const uint32_t sb = su32(sm);
    __shared__ unsigned int s_item;
    const int tid  = threadIdx.x;
    const int wid  = tid >> 5;
    const int lane = tid & 31;
    const int gid  = lane >> 2;
    const int tig  = lane & 3;

    while (true) {
        if (tid == 0) s_item = atomicAdd(&g_ctr, 1u);
        __syncthreads();
        const unsigned int item = s_item;
        if (item >= NITEMS) break;

        const int qx = 63 - (int)(item >> 3);   // heavy q-tiles first
        const int b  = (int)(item & 7);
        const int q0 = qx * BM;
        const int grow0 = q0 + wid * 16 + gid;
        const int wrow_max = q0 + wid * 16 + 15;
        const int ntile = 2 * qx + 2;           // BN=32 tiles covering [0, q0+64)

        const __nv_bfloat16* kh_g = g_kh + (size_t)b * TLEN * HEAD;
        const __nv_bfloat16* kl_g = g_kl + (size_t)b * TLEN * HEAD;
        const __half*        vh_g = g_vh + (size_t)b * TLEN * HEAD;
        const __half*        vl_g = g_vl + (size_t)b * TLEN * HEAD;

        auto stage = [&](int buf, int t) {
            const int k0 = t * BN;
            const uint32_t d0 = sb + buf * BUFB;
            #pragma unroll
            for (int ii = 0; ii < 8; ii++) {          // K hi+lo: 1024 chunks
                int i = tid + ii * 128;
                int sub = i >> 9, j = i & 511, r = j >> 4, c = j & 15;
                const __nv_bfloat16* s0 = (sub == 0 ? kh_g : kl_g) + (size_t)(k0 + r) * HEAD + c * 8;
                CP_ASYNC16(d0 + sub * BN * PITCHB + r * PITCHB + c * 16, (const void*)s0);
            }
            #pragma unroll
            for (int ii = 0; ii < 8; ii++) {          // V hi+lo
                int i = tid + ii * 128;
                int sub = i >> 9, j = i & 511, r = j >> 4, c = j & 15;
                const __half* s0 = (sub == 0 ? vh_g : vl_g) + (size_t)(k0 + r) * HEAD + c * 8;
                CP_ASYNC16(d0 + (2 + sub) * BN * PITCHB + r * PITCHB + c * 16, (const void*)s0);
            }
            CP_COMMIT();
        };

        stage(0, 0);
        stage(1, 1);

        // ---- Q fragments ----
        uint32_t aqh[8][4], aql[8][4];
        {
            const size_t rb = (size_t)b * TLEN + grow0;
            #pragma unroll
            for (int kc = 0; kc < 8; kc++) {
                const int col = kc * 16 + 2 * tig;
                aqh[kc][0] = *(const uint32_t*)(g_qh + rb * HEAD + col);
                aqh[kc][1] = *(const uint32_t*)(g_qh + (rb + 8) * HEAD + col);
                aqh[kc][2] = *(const uint32_t*)(g_qh + rb * HEAD + col + 8);
                aqh[kc][3] = *(const uint32_t*)(g_qh + (rb + 8) * HEAD + col + 8);
                aql[kc][0] = *(const uint32_t*)(g_ql + rb * HEAD + col);
                aql[kc][1] = *(const uint32_t*)(g_ql + (rb + 8) * HEAD + col);
                aql[kc][2] = *(const uint32_t*)(g_ql + rb * HEAD + col + 8);
                aql[kc][3] = *(const uint32_t*)(g_ql + (rb + 8) * HEAD + col + 8);
            }
        }

        float o[16][4];
        #pragma unroll
        for (int i = 0; i < 16; i++)
            #pragma unroll
            for (int j = 0; j < 4; j++) o[i][j] = 0.f;
        float m0 = -3.0e38f, m1 = -3.0e38f, l0 = 0.f, l1 = 0.f;
        uint32_t pfa[4], pfb[4];        // P(t) fp16 fragments (32 keys)

        for (int t = -1; t < ntile; t++) {
            CP_WAIT(0);
            __syncthreads();
            if (t >= 0 && t + 2 < ntile) stage((t + 2) % NBUF, t + 2);

            const bool qkA = (t + 1 < ntile) && (BN * (t + 1) <= wrow_max);
            const bool pvA = (t >= 0) && (BN * t <= wrow_max);
            const uint32_t KH = sb + ((t + 1) % NBUF) * BUFB;
            const uint32_t KL = KH + BN * PITCHB;
            const uint32_t VH = sb + ((t + NBUF) % NBUF) * BUFB + 2 * BN * PITCHB;
            const uint32_t VL = VH + BN * PITCHB;

            float s[4][4];
            #pragma unroll
            for (int i = 0; i < 4; i++)
                #pragma unroll
                for (int j = 0; j < 4; j++) s[i][j] = 0.f;

            // ---- interleaved: QK(t+1) + PV(t) ----
            #pragma unroll
            for (int kc = 0; kc < 8; kc++) {
                if (qkA) {
                    uint32_t kh[2][4], kl[2][4];
                    #pragma unroll
                    for (int u = 0; u < 2; u++) {
                        const int i7 = lane & 7, sel = lane >> 3;
                        const uint32_t off =
                            (uint32_t)((16 * u + i7 + ((sel >> 1) << 3)) * PITCHB +
                                       (kc * 16 + ((sel & 1) << 3)) * 2);
                        ldsm4(kh[u], KH + off);
                        ldsm4(kl[u], KL + off);
                    }
                    #pragma unroll
                    for (int term = 0; term < 3; term++) {
                        const uint32_t* a = (term == 2) ? aql[kc] : aqh[kc];
                        const uint32_t (*bb)[4] = (term == 1) ? kl : kh;
                        mma_bf16(s[0], a, &bb[0][0]);
                        mma_bf16(s[1], a, &bb[0][2]);
                        mma_bf16(s[2], a, &bb[1][0]);
                        mma_bf16(s[3], a, &bb[1][2]);
                    }
                }
                if ((kc & 3) == 3 && pvA) {          // kc = 3, 7 -> c = 0, 1
                    const int c = kc >> 2;
                    const uint32_t ah[4] = { pfa[2 * c], pfb[2 * c], pfa[2 * c + 1], pfb[2 * c + 1] };
                    #pragma unroll
                    for (int qq = 0; qq < 4; qq++) {
                        uint32_t vh[2][4], vl[2][4];
                        #pragma unroll
                        for (int u = 0; u < 2; u++) {
                            const int q = 2 * qq + u;
                            const int i7 = lane & 7, sel = lane >> 3;
                            const uint32_t off =
                                (uint32_t)((c * 16 + i7 + ((sel & 1) << 3)) * PITCHB +
                                           (16 * q + ((sel >> 1) << 3)) * 2);
                            ldsm4t(vh[u], VH + off);
                            ldsm4t(vl[u], VL + off);
                        }
                        mma_f16(o[4 * qq + 0], ah, &vh[0][0]);
                        mma_f16(o[4 * qq + 1], ah, &vh[0][2]);
                        mma_f16(o[4 * qq + 2], ah, &vh[1][0]);
                        mma_f16(o[4 * qq + 3], ah, &vh[1][2]);
                        mma_f16(o[4 * qq + 0], ah, &vl[0][0]);
                        mma_f16(o[4 * qq + 1], ah, &vl[0][2]);
                        mma_f16(o[4 * qq + 2], ah, &vl[1][0]);
                        mma_f16(o[4 * qq + 3], ah, &vl[1][2]);
                    }
                }
            }

            // ---- softmax(t+1) ----
            if (qkA) {
                const int k0n = BN * (t + 1);
                if (k0n + BN - 1 > grow0) {
                    #pragma unroll
                    for (int nb = 0; nb < 4; nb++) {
                        #pragma unroll
                        for (int j = 0; j < 2; j++) {
                            const int c = k0n + 8 * nb + 2 * tig + j;
                            if (c > grow0)     s[nb][j]     = -3.0e38f;
                            if (c > grow0 + 8) s[nb][2 + j] = -3.0e38f;
                        }
                    }
                }
                float mx0 = m0, mx1 = m1;
                #pragma unroll
                for (int nb = 0; nb < 4; nb++) {
                    mx0 = fmaxf(mx0, fmaxf(s[nb][0], s[nb][1]));
                    mx1 = fmaxf(mx1, fmaxf(s[nb][2], s[nb][3]));
                }
                mx0 = fmaxf(mx0, __shfl_xor_sync(0xffffffffu, mx0, 1));
                mx0 = fmaxf(mx0, __shfl_xor_sync(0xffffffffu, mx0, 2));
                mx1 = fmaxf(mx1, __shfl_xor_sync(0xffffffffu, mx1, 1));
                mx1 = fmaxf(mx1, __shfl_xor_sync(0xffffffffu, mx1, 2));
                const float sf0 = fexp2(m0 - mx0);
                const float sf1 = fexp2(m1 - mx1);
                float sum0 = 0.f, sum1 = 0.f;
                #pragma unroll
                for (int nb = 0; nb < 4; nb++) {
                    __half p0 = __float2half_rn(fexp2(s[nb][0] - mx0));
                    __half p1 = __float2half_rn(fexp2(s[nb][1] - mx0));
                    __half p2 = __float2half_rn(fexp2(s[nb][2] - mx1));
                    __half p3 = __float2half_rn(fexp2(s[nb][3] - mx1));
                    pfa[nb] = pack2h(p0, p1);
                    pfb[nb] = pack2h(p2, p3);
                    sum0 += __half2float(p0) + __half2float(p1);
                    sum1 += __half2float(p2) + __half2float(p3);
                }
                sum0 += __shfl_xor_sync(0xffffffffu, sum0, 1);
                sum0 += __shfl_xor_sync(0xffffffffu, sum0, 2);
                sum1 += __shfl_xor_sync(0xffffffffu, sum1, 1);
                sum1 += __shfl_xor_sync(0xffffffffu, sum1, 2);
                l0 = l0 * sf0 + sum0;  l1 = l1 * sf1 + sum1;
                m0 = mx0;  m1 = mx1;
                #pragma unroll
                for (int nb = 0; nb < 16; nb++) {
                    o[nb][0] *= sf0; o[nb][1] *= sf0;
                    o[nb][2] *= sf1; o[nb][3] *= sf1;
                }
            }
        }

        // ---- epilogue ----
        const float inv0 = 1.f / l0;
        const float inv1 = 1.f / l1;
        float* og = out + ((size_t)b * TLEN + grow0) * HEAD;
        #pragma unroll
        for (int nb = 0; nb < 16; nb++) {
            const int col = 8 * nb + 2 * tig;
            *(float2*)(og + col)            = make_float2(o[nb][0] * inv0, o[nb][1] * inv0);
            *(float2*)(og + 8 * HEAD + col) = make_float2(o[nb][2] * inv1, o[nb][3] * inv1);
        }
    }
}

// ---------------------------------------------------------------------------
extern "C" void kernel_launch(void* const* d_in, const int* in_sizes, int n_in,
                              void* d_out, int out_size)
{
    (void)in_sizes; (void)n_in; (void)out_size;
    const float* x  = (const float*)d_in[0];
    const float* Wq = (const float*)d_in[1];
    const float* Wk = (const float*)d_in[2];
    const float* Wv = (const float*)d_in[3];
    float* out = (float*)d_out;

    static int nsm = -1;
    if (nsm < 0) {
        if (cudaDeviceGetAttribute(&nsm, cudaDevAttrMultiProcessorCount, 0) != cudaSuccess
            || nsm <= 0) nsm = 148;
    }

    static bool attr_done = false;
    if (!attr_done) {
        cudaFuncSetAttribute(proj_kernel, cudaFuncAttributeMaxDynamicSharedMemorySize,
                             (int)PROJ_SMEM);
        cudaFuncSetAttribute(attn_kernel, cudaFuncAttributeMaxDynamicSharedMemorySize,
                             (int)ATTN_SMEM);
        attr_done = true;
    }

    proj_kernel<<<BT / 128, 256, PROJ_SMEM>>>(x, Wq, Wk, Wv);
    attn_kernel<<<2 * nsm, 128, ATTN_SMEM>>>(out);
}